// round 5
// baseline (speedup 1.0000x reference)
#include <cuda_runtime.h>
#include <cuda_bf16.h>

#define S 128
#define NROWS 4096
#define WPB 4                  // warps per block
#define RPB 8                  // rows per block (2 rows per warp)
#define NBLK (NROWS / RPB)     // 512 blocks

__device__ float4 g_part[NBLK];
__device__ unsigned int g_ticket;   // zero at load; reset by last block each run

__global__ void __launch_bounds__(128) loss3_fused(const float* __restrict__ outp,
                                                   const float* __restrict__ trut,
                                                   float* __restrict__ out) {
    __shared__ float so2[RPB][2 * S];   // output rows, duplicated (wrap-free)
    __shared__ float st[RPB][S];        // truth rows
    __shared__ float4 wres[RPB];
    __shared__ unsigned int sLast;

    const int tid = threadIdx.x;
    const int w = tid >> 5;       // warp id: handles rows w (A) and w+4 (B)
    const int l = tid & 31;
    const int rowA = blockIdx.x * RPB + w;
    const int rowB = rowA + WPB;
    const int wA = w, wB = w + WPB;

    // ---- prologue: 4 independent LDG.128 (MLP=4) ----
    float4 oA = *(const float4*)(outp + rowA * S + 4 * l);
    float4 tA = *(const float4*)(trut + rowA * S + 4 * l);
    float4 oB = *(const float4*)(outp + rowB * S + 4 * l);
    float4 tB = *(const float4*)(trut + rowB * S + 4 * l);
    *(float4*)&so2[wA][4 * l]     = oA;
    *(float4*)&so2[wA][S + 4 * l] = oA;
    *(float4*)&st[wA][4 * l]      = tA;
    *(float4*)&so2[wB][4 * l]     = oB;
    *(float4*)&so2[wB][S + 4 * l] = oB;
    *(float4*)&st[wB][4 * l]      = tB;
    __syncwarp();

    // ---- per-row MSE, max(o), max(t): 6 independent shuffle chains ----
    float dAx = oA.x - tA.x, dAy = oA.y - tA.y, dAz = oA.z - tA.z, dAw = oA.w - tA.w;
    float dBx = oB.x - tB.x, dBy = oB.y - tB.y, dBz = oB.z - tB.z, dBw = oB.w - tB.w;
    float msA = dAx * dAx + dAy * dAy + dAz * dAz + dAw * dAw;
    float msB = dBx * dBx + dBy * dBy + dBz * dBz + dBw * dBw;
    float moA = fmaxf(fmaxf(oA.x, oA.y), fmaxf(oA.z, oA.w));
    float moB = fmaxf(fmaxf(oB.x, oB.y), fmaxf(oB.z, oB.w));
    float mtA = fmaxf(fmaxf(tA.x, tA.y), fmaxf(tA.z, tA.w));
    float mtB = fmaxf(fmaxf(tB.x, tB.y), fmaxf(tB.z, tB.w));
#pragma unroll
    for (int s = 16; s > 0; s >>= 1) {
        msA += __shfl_xor_sync(0xffffffffu, msA, s);
        msB += __shfl_xor_sync(0xffffffffu, msB, s);
        moA = fmaxf(moA, __shfl_xor_sync(0xffffffffu, moA, s));
        moB = fmaxf(moB, __shfl_xor_sync(0xffffffffu, moB, s));
        mtA = fmaxf(mtA, __shfl_xor_sync(0xffffffffu, mtA, s));
        mtB = fmaxf(mtB, __shfl_xor_sync(0xffffffffu, mtB, s));
    }

    // ---- circular correlation, rows A and B interleaved ----
    // acc[k] = sum_j o[(j-(4l+k))&127] * t[j];  o[(j-s)&127] = so2[j-s+S]
    const float* obA = &so2[wA][S - 4 * l - 4];
    const float* tbA = &st[wA][0];
    const float* obB = &so2[wB][S - 4 * l - 4];
    const float* tbB = &st[wB][0];
    float aA0 = 0.f, aA1 = 0.f, aA2 = 0.f, aA3 = 0.f;
    float aB0 = 0.f, aB1 = 0.f, aB2 = 0.f, aB3 = 0.f;
    float4 WA0 = *(const float4*)(obA);
    float4 WB0 = *(const float4*)(obB);
#pragma unroll
    for (int J = 0; J < S; J += 4) {
        float4 WA1 = *(const float4*)(obA + J + 4);
        float4 TTA = *(const float4*)(tbA + J);     // uniform -> broadcast
        float4 WB1 = *(const float4*)(obB + J + 4);
        float4 TTB = *(const float4*)(tbB + J);
        aA0 = fmaf(WA1.x, TTA.x, aA0);
        aB0 = fmaf(WB1.x, TTB.x, aB0);
        aA1 = fmaf(WA0.w, TTA.x, aA1);
        aB1 = fmaf(WB0.w, TTB.x, aB1);
        aA2 = fmaf(WA0.z, TTA.x, aA2);
        aB2 = fmaf(WB0.z, TTB.x, aB2);
        aA3 = fmaf(WA0.y, TTA.x, aA3);
        aB3 = fmaf(WB0.y, TTB.x, aB3);
        aA0 = fmaf(WA1.y, TTA.y, aA0);
        aB0 = fmaf(WB1.y, TTB.y, aB0);
        aA1 = fmaf(WA1.x, TTA.y, aA1);
        aB1 = fmaf(WB1.x, TTB.y, aB1);
        aA2 = fmaf(WA0.w, TTA.y, aA2);
        aB2 = fmaf(WB0.w, TTB.y, aB2);
        aA3 = fmaf(WA0.z, TTA.y, aA3);
        aB3 = fmaf(WB0.z, TTB.y, aB3);
        aA0 = fmaf(WA1.z, TTA.z, aA0);
        aB0 = fmaf(WB1.z, TTB.z, aB0);
        aA1 = fmaf(WA1.y, TTA.z, aA1);
        aB1 = fmaf(WB1.y, TTB.z, aB1);
        aA2 = fmaf(WA1.x, TTA.z, aA2);
        aB2 = fmaf(WB1.x, TTB.z, aB2);
        aA3 = fmaf(WA0.w, TTA.z, aA3);
        aB3 = fmaf(WB0.w, TTB.z, aB3);
        aA0 = fmaf(WA1.w, TTA.w, aA0);
        aB0 = fmaf(WB1.w, TTB.w, aB0);
        aA1 = fmaf(WA1.z, TTA.w, aA1);
        aB1 = fmaf(WB1.z, TTB.w, aB1);
        aA2 = fmaf(WA1.y, TTA.w, aA2);
        aB2 = fmaf(WB1.y, TTB.w, aB2);
        aA3 = fmaf(WA1.x, TTA.w, aA3);
        aB3 = fmaf(WB1.x, TTB.w, aB3);
        WA0 = WA1;
        WB0 = WB1;
    }

    // ---- argmax corr (tie -> smaller shift): two interleaved chains ----
    float bcA = aA0; int bsA = 4 * l;
    float bcB = aB0; int bsB = 4 * l;
    if (aA1 > bcA) { bcA = aA1; bsA = 4 * l + 1; }
    if (aB1 > bcB) { bcB = aB1; bsB = 4 * l + 1; }
    if (aA2 > bcA) { bcA = aA2; bsA = 4 * l + 2; }
    if (aB2 > bcB) { bcB = aB2; bsB = 4 * l + 2; }
    if (aA3 > bcA) { bcA = aA3; bsA = 4 * l + 3; }
    if (aB3 > bcB) { bcB = aB3; bsB = 4 * l + 3; }
#pragma unroll
    for (int s = 16; s > 0; s >>= 1) {
        float ocA = __shfl_xor_sync(0xffffffffu, bcA, s);
        int   osA = __shfl_xor_sync(0xffffffffu, bsA, s);
        float ocB = __shfl_xor_sync(0xffffffffu, bcB, s);
        int   osB = __shfl_xor_sync(0xffffffffu, bsB, s);
        if (ocA > bcA || (ocA == bcA && osA < bsA)) { bcA = ocA; bsA = osA; }
        if (ocB > bcB || (ocB == bcB && osB < bsB)) { bcB = ocB; bsB = osB; }
    }
    const int bA = bsA, bB = bsB;
    const float scaleA = mtA / moA;   // max(rolled)==max(output): roll is a permutation
    const float scaleB = mtB / moB;

    // ---- detail loss: g = cgrad(rolled*scale - truth); both rows ----
    float ggA = 0.f, ggB = 0.f;
#pragma unroll
    for (int m = 0; m < 4; m++) {
        int i = 4 * l + m;
        float am1 = so2[wA][(i - 1 - bA) & 127] * scaleA - st[wA][(i - 1) & 127];
        float ac0 = so2[wA][(i     - bA) & 127] * scaleA - st[wA][i];
        float ap1 = so2[wA][(i + 1 - bA) & 127] * scaleA - st[wA][(i + 1) & 127];
        float bm1 = so2[wB][(i - 1 - bB) & 127] * scaleB - st[wB][(i - 1) & 127];
        float bc0 = so2[wB][(i     - bB) & 127] * scaleB - st[wB][i];
        float bp1 = so2[wB][(i + 1 - bB) & 127] * scaleB - st[wB][(i + 1) & 127];
        float gA = ac0 - 0.5f * (am1 + ap1);
        float gB = bc0 - 0.5f * (bm1 + bp1);
        ggA = fmaf(gA, gA, ggA);
        ggB = fmaf(gB, gB, ggB);
    }
#pragma unroll
    for (int s = 16; s > 0; s >>= 1) {
        ggA += __shfl_xor_sync(0xffffffffu, ggA, s);
        ggB += __shfl_xor_sync(0xffffffffu, ggB, s);
    }

    // ---- per-block partial (fixed order over 8 rows) ----
    if (l == 0) {
        wres[wA] = make_float4((float)bA, fabsf(scaleA - 1.0f), sqrtf(ggA), msA);
        wres[wB] = make_float4((float)bB, fabsf(scaleB - 1.0f), sqrtf(ggB), msB);
    }
    __syncthreads();
    if (tid == 0) {
        float4 r = wres[0];
#pragma unroll
        for (int k = 1; k < RPB; k++) {
            float4 q = wres[k];
            r.x += q.x; r.y += q.y; r.z += q.z; r.w += q.w;
        }
        g_part[blockIdx.x] = r;
        __threadfence();
        unsigned int old = atomicAdd(&g_ticket, 1u);
        sLast = (old == NBLK - 1) ? 1u : 0u;
    }
    __syncthreads();

    // ---- last block finalizes (deterministic fixed-order reduction) ----
    if (sLast) {
        float a = 0.f, bb = 0.f, c = 0.f, dd = 0.f;
#pragma unroll
        for (int i = tid; i < NBLK; i += 128) {
            float4 q = g_part[i];
            a += q.x; bb += q.y; c += q.z; dd += q.w;
        }
        float4* fr = (float4*)&so2[0][0];   // reuse smem
        fr[tid] = make_float4(a, bb, c, dd);
        __syncthreads();
#pragma unroll
        for (int stp = 64; stp > 0; stp >>= 1) {
            if (tid < stp) {
                float4 x = fr[tid], y = fr[tid + stp];
                fr[tid] = make_float4(x.x + y.x, x.y + y.y, x.z + y.z, x.w + y.w);
            }
            __syncthreads();
        }
        if (tid == 0) {
            float4 r = fr[0];
            out[0] = 50.0f * r.x + 100.0f * r.y + 0.1f * r.z + sqrtf(r.w);
            g_ticket = 0u;   // reset for next graph replay
        }
    }
}

extern "C" void kernel_launch(void* const* d_in, const int* in_sizes, int n_in,
                              void* d_out, int out_size) {
    (void)n_in; (void)out_size; (void)in_sizes;
    const float* outp = (const float*)d_in[0];
    const float* trut = (const float*)d_in[1];
    float* res = (float*)d_out;
    loss3_fused<<<NBLK, 128>>>(outp, trut, res);
}

// round 6
// speedup vs baseline: 1.1567x; 1.1567x over previous
#include <cuda_runtime.h>
#include <cuda_bf16.h>

#define S 128
#define NROWS 4096
#define RPB 4                 // rows per block (one warp per row)
#define NBLK (NROWS / RPB)    // 1024 blocks

__device__ float4 g_part[NBLK];
__device__ unsigned int g_ticket;   // zero at load; reset by last block each run

__device__ __forceinline__ void fma2(unsigned long long& c,
                                     unsigned long long a,
                                     unsigned long long b) {
    asm("fma.rn.f32x2 %0, %1, %2, %0;" : "+l"(c) : "l"(a), "l"(b));
}
__device__ __forceinline__ float2 unpk(unsigned long long v) {
    float2 r;
    asm("mov.b64 {%0, %1}, %2;" : "=f"(r.x), "=f"(r.y) : "l"(v));
    return r;
}

__global__ void __launch_bounds__(128) loss3_fused(const float* __restrict__ outp,
                                                   const float* __restrict__ trut,
                                                   float* __restrict__ out) {
    __shared__ float so2[RPB][2 * S];   // output row, duplicated (wrap-free)
    __shared__ float st[RPB][S];        // truth row
    __shared__ float4 wres[RPB];
    __shared__ unsigned int sLast;

    const int tid = threadIdx.x;
    const int w = tid >> 5;     // warp = row within block
    const int l = tid & 31;     // lane
    const int row = blockIdx.x * RPB + w;

    // ---- load row (coalesced float4), mirror into smem ----
    float4 o4 = *(const float4*)(outp + row * S + 4 * l);
    float4 t4 = *(const float4*)(trut + row * S + 4 * l);
    *(float4*)&so2[w][4 * l]     = o4;
    *(float4*)&so2[w][S + 4 * l] = o4;
    *(float4*)&st[w][4 * l]      = t4;
    __syncwarp();

    // ---- row MSE (direct), max(output), max(truth): warp shuffles ----
    float d0 = o4.x - t4.x, d1 = o4.y - t4.y, d2 = o4.z - t4.z, d3 = o4.w - t4.w;
    float ms = d0 * d0 + d1 * d1 + d2 * d2 + d3 * d3;
    float mo = fmaxf(fmaxf(o4.x, o4.y), fmaxf(o4.z, o4.w));
    float mt = fmaxf(fmaxf(t4.x, t4.y), fmaxf(t4.z, t4.w));
#pragma unroll
    for (int s = 16; s > 0; s >>= 1) {
        ms += __shfl_xor_sync(0xffffffffu, ms, s);
        mo = fmaxf(mo, __shfl_xor_sync(0xffffffffu, mo, s));
        mt = fmaxf(mt, __shfl_xor_sync(0xffffffffu, mt, s));
    }

    // ---- circular correlation: acc[k] = sum_j o[(j-(4l+k))&127] * t[j] ----
    // o[(j-s)&127] = so2[j - s + S].  base = S - 4l - 4 (16B aligned).
    // k=0,2 accumulate as packed f32x2 (even/odd j lanes); all their operand
    // pairs are aligned register pairs from the LDS.128 -> zero packing.
    // k=1,3 stay scalar FFMA (misaligned pairs).
    const float* ob = &so2[w][S - 4 * l - 4];
    const float* tb = &st[w][0];
    unsigned long long A0 = 0ull, A2 = 0ull;
    float acc1 = 0.f, acc3 = 0.f;
    ulonglong2 Wp = *(const ulonglong2*)(ob);   // {W0,W1},{W2,W3}
    float2 pwx = unpk(Wp.x);                    // W0,W1
    float2 pwy = unpk(Wp.y);                    // W2,W3
#pragma unroll
    for (int J = 0; J < S; J += 4) {
        ulonglong2 Wd = *(const ulonglong2*)(ob + J + 4);  // {W4,W5},{W6,W7}
        ulonglong2 Td = *(const ulonglong2*)(tb + J);      // {t0,t1},{t2,t3}
        float2 wx = unpk(Wd.x);   // W4,W5 (register renames)
        float2 wy = unpk(Wd.y);   // W6,W7
        float2 tx = unpk(Td.x);   // t0,t1
        float2 ty = unpk(Td.y);   // t2,t3
        fma2(A0, Wd.x, Td.x);     // k=0: W4*t0 | W5*t1
        fma2(A0, Wd.y, Td.y);     //      W6*t2 | W7*t3
        fma2(A2, Wp.y, Td.x);     // k=2: W2*t0 | W3*t1
        fma2(A2, Wd.x, Td.y);     //      W4*t2 | W5*t3
        acc1 = fmaf(pwy.y, tx.x, acc1);   // k=1: W3*t0
        acc1 = fmaf(wx.x,  tx.y, acc1);   //      W4*t1
        acc1 = fmaf(wx.y,  ty.x, acc1);   //      W5*t2
        acc1 = fmaf(wy.x,  ty.y, acc1);   //      W6*t3
        acc3 = fmaf(pwx.y, tx.x, acc3);   // k=3: W1*t0
        acc3 = fmaf(pwy.x, tx.y, acc3);   //      W2*t1
        acc3 = fmaf(pwy.y, ty.x, acc3);   //      W3*t2
        acc3 = fmaf(wx.x,  ty.y, acc3);   //      W4*t3
        Wp = Wd; pwx = wx; pwy = wy;
    }
    float2 a0p = unpk(A0);
    float2 a2p = unpk(A2);
    float acc0 = a0p.x + a0p.y;
    float acc2 = a2p.x + a2p.y;

    // ---- argmax corr == argmin shiftDiff; tie-break -> smaller shift ----
    float bc = acc0; int bs = 4 * l;
    if (acc1 > bc) { bc = acc1; bs = 4 * l + 1; }
    if (acc2 > bc) { bc = acc2; bs = 4 * l + 2; }
    if (acc3 > bc) { bc = acc3; bs = 4 * l + 3; }
#pragma unroll
    for (int s = 16; s > 0; s >>= 1) {
        float oc = __shfl_xor_sync(0xffffffffu, bc, s);
        int   os = __shfl_xor_sync(0xffffffffu, bs, s);
        if (oc > bc || (oc == bc && os < bs)) { bc = oc; bs = os; }
    }
    const int b = bs;
    const float scale = mt / mo;   // max(rolled) == max(output): roll is a permutation

    // ---- detail loss: g = cgrad(rolled*scale - truth), cgrad linear ----
    // d[i] = o[(i-b)&127]*scale - t[i]; each lane computes its 4 own d's
    // (t from registers), boundary neighbors via 2 shuffles.
    float dd0 = so2[w][(4 * l     - b) & 127] * scale - t4.x;
    float dd1 = so2[w][(4 * l + 1 - b) & 127] * scale - t4.y;
    float dd2 = so2[w][(4 * l + 2 - b) & 127] * scale - t4.z;
    float dd3 = so2[w][(4 * l + 3 - b) & 127] * scale - t4.w;
    float dm = __shfl_sync(0xffffffffu, dd3, (l + 31) & 31);  // d[4l-1] (circular)
    float dp = __shfl_sync(0xffffffffu, dd0, (l + 1) & 31);   // d[4l+4] (circular)
    float g0 = dd0 - 0.5f * (dm  + dd1);
    float g1 = dd1 - 0.5f * (dd0 + dd2);
    float g2 = dd2 - 0.5f * (dd1 + dd3);
    float g3 = dd3 - 0.5f * (dd2 + dp);
    float gg = fmaf(g0, g0, fmaf(g1, g1, fmaf(g2, g2, g3 * g3)));
#pragma unroll
    for (int s = 16; s > 0; s >>= 1) gg += __shfl_xor_sync(0xffffffffu, gg, s);

    // ---- per-block partial (fixed order: warp 0..3) ----
    if (l == 0) wres[w] = make_float4((float)b, fabsf(scale - 1.0f), sqrtf(gg), ms);
    __syncthreads();
    if (tid == 0) {
        float4 r = wres[0];
#pragma unroll
        for (int k = 1; k < RPB; k++) {
            float4 q = wres[k];
            r.x += q.x; r.y += q.y; r.z += q.z; r.w += q.w;
        }
        g_part[blockIdx.x] = r;
        __threadfence();
        unsigned int old = atomicAdd(&g_ticket, 1u);
        sLast = (old == NBLK - 1) ? 1u : 0u;
    }
    __syncthreads();

    // ---- last block finalizes (deterministic fixed-order reduction) ----
    if (sLast) {
        float a = 0.f, bb = 0.f, c = 0.f, dd = 0.f;
#pragma unroll
        for (int i = tid; i < NBLK; i += 128) {
            float4 q = g_part[i];
            a += q.x; bb += q.y; c += q.z; dd += q.w;
        }
        float4* fr = (float4*)&so2[0][0];   // reuse smem
        fr[tid] = make_float4(a, bb, c, dd);
        __syncthreads();
#pragma unroll
        for (int stp = 64; stp > 0; stp >>= 1) {
            if (tid < stp) {
                float4 x = fr[tid], y = fr[tid + stp];
                fr[tid] = make_float4(x.x + y.x, x.y + y.y, x.z + y.z, x.w + y.w);
            }
            __syncthreads();
        }
        if (tid == 0) {
            float4 r = fr[0];
            out[0] = 50.0f * r.x + 100.0f * r.y + 0.1f * r.z + sqrtf(r.w);
            g_ticket = 0u;   // reset for next graph replay
        }
    }
}

extern "C" void kernel_launch(void* const* d_in, const int* in_sizes, int n_in,
                              void* d_out, int out_size) {
    (void)n_in; (void)out_size; (void)in_sizes;
    const float* outp = (const float*)d_in[0];
    const float* trut = (const float*)d_in[1];
    float* res = (float*)d_out;
    loss3_fused<<<NBLK, 128>>>(outp, trut, res);
}